// round 11
// baseline (speedup 1.0000x reference)
#include <cuda_runtime.h>
#include <cuda_bf16.h>
#include <cstdint>

typedef unsigned long long u64;

// ---------------- config ----------------
constexpr int TPB = 256;        // 8 warps
constexpr int EPB = 256;        // 1 edge per thread; warp owns 32 edges

// smem byte offsets
constexpr int OFF_AFH = 0;               // A-frags hi: 9216 u32 = 36864B
constexpr int OFF_AFL = 36864;           // A-frags lo: 36864B
constexpr int OFF_HHI = 73728;           // h hi: 256 edges x 35 u32 = 35840B
constexpr int OFF_HLO = 109568;          // h lo: 35840B
constexpr int OFF_TP  = 145408;          // tp: 256 x 16 f32 = 16384B
constexpr int OFF_BUF = 161792;          // 8 warps x 288 f32 = 9216B (stride 36 rows)
constexpr int OFF_BES = 171008;          // bessel W0 rows: 512 f32 = 2048B
constexpr int OFF_CST = 173056;          // 16 f32
constexpr int SMEM_BYTES = 173120;

constexpr int BSTR = 36;                 // D-buf row stride in floats (16B aligned)

// ---------------- device scratch ----------------
__device__ float    g_wcombo[64 * 160];
__device__ uint32_t g_afrag_hi[9216];    // 18 mtiles x 4 ktiles x 32 lanes x 4 regs
__device__ uint32_t g_afrag_lo[9216];

__device__ __forceinline__ float silu_f(float v) { return v / (1.0f + __expf(-v)); }

// ---------------- prep 1: W_combo = (W1*S1) @ (We*S2) ----------------
// block = one r row (64 blocks), 160 threads = one c each; We reads coalesced.
__global__ void combo_kernel(const float* __restrict__ W1, const float* __restrict__ We) {
    constexpr float S1 = 1.6789f * 0.125f;
    constexpr float S2 = 0.08838834764831845f;
    __shared__ float w1row[128];
    const int r = blockIdx.x;
    const int c = threadIdx.x;
    if (c < 128) w1row[c] = W1[r * 128 + c];
    __syncthreads();
    float acc = 0.0f;
#pragma unroll 8
    for (int k = 0; k < 128; k++)
        acc = fmaf(w1row[k], __ldg(We + k * 160 + c), acc);
    g_wcombo[r * 160 + c] = acc * (S1 * S2);
}

// packed weight element A[m][k] (A = Bpack^T), m in [0,288)
__device__ __forceinline__ float apack_val(int k, int m, const float* __restrict__ W1) {
    constexpr float S1 = 1.6789f * 0.125f;
    if (m < 128) return W1[k * 128 + m] * S1;
    if (m < 192) { int p = (m - 128) >> 1, s = (m - 128) & 1; return g_wcombo[k * 160 + p + 32 * s]; }
    if (m < 256) { int p = (m - 192) >> 1, s = (m - 192) & 1; return g_wcombo[k * 160 + 64 + p + 32 * s]; }
    return g_wcombo[k * 160 + 128 + (m - 256)];
}

// ---------------- prep 2: A fragments (hi/lo bf16) in mma order ----------------
__global__ void afrag_kernel(const float* __restrict__ W1) {
    int idx = blockIdx.x * blockDim.x + threadIdx.x;
    if (idx >= 9216) return;
    int ri = idx & 3, t = (idx >> 2) & 31, kt = (idx >> 7) & 3, mt = idx >> 9;
    int m  = mt * 16 + (t >> 2) + (ri & 1) * 8;
    int k0 = kt * 16 + (t & 3) * 2 + (ri >> 1) * 8;
    uint32_t hi = 0, lo = 0;
#pragma unroll
    for (int hv = 0; hv < 2; hv++) {
        float val = apack_val(k0 + hv, m, W1);
        __nv_bfloat16 h = __float2bfloat16(val);
        float rem = val - __bfloat162float(h);
        __nv_bfloat16 l = __float2bfloat16(rem);
        hi |= (uint32_t)__bfloat16_as_ushort(h) << (16 * hv);
        lo |= (uint32_t)__bfloat16_as_ushort(l) << (16 * hv);
    }
    g_afrag_hi[idx] = hi;
    g_afrag_lo[idx] = lo;
}

// ---------------- mma helper ----------------
__device__ __forceinline__ void mma16816(float* d, const uint4& a, uint32_t b0, uint32_t b1) {
    asm volatile(
        "mma.sync.aligned.m16n8k16.row.col.f32.bf16.bf16.f32 "
        "{%0,%1,%2,%3}, {%4,%5,%6,%7}, {%8,%9}, {%0,%1,%2,%3};"
        : "+f"(d[0]), "+f"(d[1]), "+f"(d[2]), "+f"(d[3])
        : "r"(a.x), "r"(a.y), "r"(a.z), "r"(a.w), "r"(b0), "r"(b1));
}

// ---------------- main kernel ----------------
__global__ void __launch_bounds__(TPB, 1)
e3_mma_kernel(const int*   __restrict__ eidx,
              const float* __restrict__ esh,
              const float* __restrict__ elen,
              const float* __restrict__ onehot,
              const float* __restrict__ bw,
              const float* __restrict__ tpw,
              const float* __restrict__ W0,
              float*       __restrict__ out,
              int E)
{
    extern __shared__ __align__(16) char smc[];
    const int tid  = threadIdx.x;
    const int warp = tid >> 5;
    const int lane = tid & 31;
    const int t3   = lane & 3;
    const int g    = lane >> 2;

    // ---- cooperative loads ----
    {
        uint4* afh = reinterpret_cast<uint4*>(smc + OFF_AFH);
        uint4* afl = reinterpret_cast<uint4*>(smc + OFF_AFL);
        const uint4* gh = reinterpret_cast<const uint4*>(g_afrag_hi);
        const uint4* gl = reinterpret_cast<const uint4*>(g_afrag_lo);
#pragma unroll
        for (int i = 0; i < 9; i++) {                 // 2304 uint4 each
            afh[tid + i * TPB] = gh[tid + i * TPB];
            afl[tid + i * TPB] = gl[tid + i * TPB];
        }
        float* bes = reinterpret_cast<float*>(smc + OFF_BES);
        bes[tid]       = W0[32 * 64 + tid];
        bes[tid + 256] = W0[32 * 64 + 256 + tid];
        float* cst = reinterpret_cast<float*>(smc + OFF_CST);
        if (tid < 8)       cst[tid] = bw[tid];
        else if (tid < 15) cst[tid] = tpw[tid - 8];
    }
    __syncthreads();

    const float* bes = reinterpret_cast<const float*>(smc + OFF_BES);
    const float* cst = reinterpret_cast<const float*>(smc + OFF_CST);
    float* tparr = reinterpret_cast<float*>(smc + OFF_TP);

    float* __restrict__ lat_out  = out;
    float* __restrict__ feat_out = out + (size_t)E * 128;
    float* __restrict__ cut_out  = out + (size_t)E * 416;

    // ================= stage 1: per-thread edge =================
    {
        const int e = blockIdx.x * EPB + tid;
        const int   src = eidx[e];
        const int   dst = eidx[E + e];
        const float r   = elen[e];
        const float4 shv = reinterpret_cast<const float4*>(esh)[e];

        int ts = 0, td = 0;
        {
            const float4* rs = reinterpret_cast<const float4*>(onehot + (size_t)src * 16);
            const float4* rd = reinterpret_cast<const float4*>(onehot + (size_t)dst * 16);
#pragma unroll
            for (int q4 = 0; q4 < 4; q4++) {
                float4 a = __ldg(rs + q4); float4 b = __ldg(rd + q4);
                int base = q4 * 4;
                if (a.x > 0.5f) ts = base;     if (a.y > 0.5f) ts = base + 1;
                if (a.z > 0.5f) ts = base + 2; if (a.w > 0.5f) ts = base + 3;
                if (b.x > 0.5f) td = base;     if (b.y > 0.5f) td = base + 1;
                if (b.z > 0.5f) td = base + 2; if (b.w > 0.5f) td = base + 3;
            }
        }

        const float x    = r * 0.2f;
        const float invr = 1.0f / r;
        float eb[8];
#pragma unroll
        for (int j = 0; j < 8; j++)
            eb[j] = 0.4f * __sinf(cst[j] * x) * invr;

        const float x3 = x * x * x, x6 = x3 * x3, x7 = x6 * x, x8 = x7 * x;
        const float poly = 1.0f - 28.0f * x6 + 48.0f * x7 - 21.0f * x8;
        const float cutv = (x < 1.0f) ? poly : 0.0f;
        const float cl   = (cutv > 0.0f) ? cutv : 0.0f;
        cut_out[e] = cutv;

        // h = silu(S0*(W0[ts] + W0[16+td] + eb @ bessel_rows))
        constexpr float S0 = 0.15811388300841897f;
        float h[64];
        {
            const float4* rowts = reinterpret_cast<const float4*>(W0 + ts * 64);
            const float4* rowtd = reinterpret_cast<const float4*>(W0 + (16 + td) * 64);
#pragma unroll
            for (int q = 0; q < 16; q++) {
                float4 a = __ldg(rowts + q);
                float4 b = __ldg(rowtd + q);
                h[4 * q + 0] = a.x + b.x; h[4 * q + 1] = a.y + b.y;
                h[4 * q + 2] = a.z + b.z; h[4 * q + 3] = a.w + b.w;
            }
#pragma unroll
            for (int j = 0; j < 8; j++) {
                const float bj = eb[j];
                const float4* br = reinterpret_cast<const float4*>(bes + j * 64);
#pragma unroll
                for (int q = 0; q < 16; q++) {
                    float4 w = br[q];
                    h[4 * q + 0] = fmaf(bj, w.x, h[4 * q + 0]);
                    h[4 * q + 1] = fmaf(bj, w.y, h[4 * q + 1]);
                    h[4 * q + 2] = fmaf(bj, w.z, h[4 * q + 2]);
                    h[4 * q + 3] = fmaf(bj, w.w, h[4 * q + 3]);
                }
            }
        }

        // split h -> bf16 hi/lo; store pairs (stride 35 u32 per edge)
        uint32_t* hhw = reinterpret_cast<uint32_t*>(smc + OFF_HHI) + tid * 35;
        uint32_t* hlw = reinterpret_cast<uint32_t*>(smc + OFF_HLO) + tid * 35;
#pragma unroll
        for (int q = 0; q < 32; q++) {
            float v0 = silu_f(S0 * h[2 * q]);
            float v1 = silu_f(S0 * h[2 * q + 1]);
            __nv_bfloat16 h0 = __float2bfloat16(v0), h1 = __float2bfloat16(v1);
            float r0 = v0 - __bfloat162float(h0);
            float r1 = v1 - __bfloat162float(h1);
            __nv_bfloat16 l0 = __float2bfloat16(r0), l1 = __float2bfloat16(r1);
            hhw[q] = (uint32_t)__bfloat16_as_ushort(h0) | ((uint32_t)__bfloat16_as_ushort(h1) << 16);
            hlw[q] = (uint32_t)__bfloat16_as_ushort(l0) | ((uint32_t)__bfloat16_as_ushort(l1) << 16);
        }

        // tp scalars (cut + INV2 folded)
        constexpr float SQ3  = 1.7320508075688772f;
        constexpr float INV2 = 0.70710678118654752f;
        const float s = shv.x, vx = shv.y, vy = shv.z, vz = shv.w;
        const float tw0 = cst[8],  tw1 = cst[9],  tw2 = cst[10];
        const float tw3 = cst[11], tw4 = cst[12], tw5 = cst[13];
        const float tw6 = cst[14];
        const float sq   = s * s;
        const float dotv = (vx * vx + vy * vy + vz * vz) * (1.0f / SQ3);
        float* tp = tparr + tid * 16;
        tp[0] = cl;
        tp[1] = INV2 * (tw0 * sq + tw1 * dotv) * cl;
        tp[2] = INV2 * (tw4 * sq + tw5 * dotv) * cl;
        const float sa = INV2 * tw2 * s * cl;
        const float sb = INV2 * tw3 * s * cl;
        tp[3] = sa * vx; tp[4] = sa * vy; tp[5] = sa * vz;
        tp[6] = sb * vx; tp[7] = sb * vy; tp[8] = sb * vz;
        const float t6c = tw6 * cl;
        tp[9]  = t6c * SQ3 * vx * vy;
        tp[10] = t6c * SQ3 * vy * vz;
        tp[11] = t6c * (vz * vz - 0.5f * (vx * vx + vy * vy));
        tp[12] = t6c * SQ3 * vx * vz;
        tp[13] = t6c * (0.5f * SQ3) * (vx * vx - vy * vy);
    }
    __syncwarp();   // h/tp written & read within the same warp

    // ================= GEMM via mma.sync =================
    const uint4* afh = reinterpret_cast<const uint4*>(smc + OFF_AFH);
    const uint4* afl = reinterpret_cast<const uint4*>(smc + OFF_AFL);
    const uint32_t* hh = reinterpret_cast<const uint32_t*>(smc + OFF_HHI);
    const uint32_t* hl = reinterpret_cast<const uint32_t*>(smc + OFF_HLO);
    float* bwarp = reinterpret_cast<float*>(smc + OFF_BUF) + warp * (8 * BSTR);

    // ---- hoist all B fragments into registers (c-invariant) ----
    // ngroup ng covers edges warp*32 + ng*8 + {0..7}; this thread's B col = g.
    uint32_t Bh[4][4][2], Bl[4][4][2];
#pragma unroll
    for (int ng = 0; ng < 4; ng++) {
        const int eb = (warp * 32 + ng * 8 + g) * 35 + t3;
#pragma unroll
        for (int kt = 0; kt < 4; kt++) {
            Bh[ng][kt][0] = hh[eb + kt * 8];
            Bh[ng][kt][1] = hh[eb + kt * 8 + 4];
            Bl[ng][kt][0] = hl[eb + kt * 8];
            Bl[ng][kt][1] = hl[eb + kt * 8 + 4];
        }
    }

#pragma unroll 1
    for (int c = 0; c < 9; c++) {
        float acc[4][2][4];
#pragma unroll
        for (int n = 0; n < 4; n++)
#pragma unroll
            for (int m = 0; m < 2; m++)
#pragma unroll
                for (int q = 0; q < 4; q++) acc[n][m][q] = 0.0f;

#pragma unroll
        for (int kt = 0; kt < 4; kt++) {
            const int ai = (2 * c * 4 + kt) * 32 + lane;
            const uint4 ah0 = afh[ai];
            const uint4 ah1 = afh[ai + 128];
            const uint4 al0 = afl[ai];
            const uint4 al1 = afl[ai + 128];
#pragma unroll
            for (int ng = 0; ng < 4; ng++) {
                const uint32_t bha = Bh[ng][kt][0], bhb = Bh[ng][kt][1];
                const uint32_t bla = Bl[ng][kt][0], blb = Bl[ng][kt][1];
                mma16816(acc[ng][0], ah0, bha, bhb);
                mma16816(acc[ng][1], ah1, bha, bhb);
                mma16816(acc[ng][0], ah0, bla, blb);
                mma16816(acc[ng][1], ah1, bla, blb);
                mma16816(acc[ng][0], al0, bha, bhb);
                mma16816(acc[ng][1], al1, bha, bhb);
            }
        }

        // ---- epilogue per ngroup ----
#pragma unroll 1
        for (int ng = 0; ng < 4; ng++) {
            // scatter D frags to buf[edge][m] (stride BSTR)
#pragma unroll
            for (int mtc = 0; mtc < 2; mtc++) {
                bwarp[(2 * t3)     * BSTR + mtc * 16 + g]     = acc[ng][mtc][0];
                bwarp[(2 * t3 + 1) * BSTR + mtc * 16 + g]     = acc[ng][mtc][1];
                bwarp[(2 * t3)     * BSTR + mtc * 16 + g + 8] = acc[ng][mtc][2];
                bwarp[(2 * t3 + 1) * BSTR + mtc * 16 + g + 8] = acc[ng][mtc][3];
            }
            __syncwarp();

            const int el = warp * 32 + ng * 8 + g;          // block-local edge
            const size_t eg = (size_t)blockIdx.x * EPB + el;
            const float* tp  = tparr + el * 16;
            const float* row = bwarp + g * BSTR;

            if (c < 4) {
                const float cl = tp[0];
#pragma unroll
                for (int h2 = 0; h2 < 2; h2++) {
                    float4 v = *reinterpret_cast<const float4*>(row + t3 * 8 + 4 * h2);
                    v.x *= cl; v.y *= cl; v.z *= cl; v.w *= cl;
                    *reinterpret_cast<float4*>(lat_out + eg * 128 + c * 32 + t3 * 8 + 4 * h2) = v;
                }
            } else if (c < 6) {
                const float ta = tp[1], tb = tp[2];
                float4 v;
                v.x = row[8 * t3 + 0] * ta + row[8 * t3 + 1] * tb;
                v.y = row[8 * t3 + 2] * ta + row[8 * t3 + 3] * tb;
                v.z = row[8 * t3 + 4] * ta + row[8 * t3 + 5] * tb;
                v.w = row[8 * t3 + 6] * ta + row[8 * t3 + 7] * tb;
                *reinterpret_cast<float4*>(feat_out + eg * 288 + (c - 4) * 16 + 4 * t3) = v;
            } else if (c < 8) {
                float v[12];
#pragma unroll
                for (int j = 0; j < 4; j++) {
                    const float a = row[8 * t3 + 2 * j], b = row[8 * t3 + 2 * j + 1];
                    v[3 * j + 0] = a * tp[3] + b * tp[6];
                    v[3 * j + 1] = a * tp[4] + b * tp[7];
                    v[3 * j + 2] = a * tp[5] + b * tp[8];
                }
                float* dst = feat_out + eg * 288 + 32 + (c - 6) * 48 + 12 * t3;
#pragma unroll
                for (int t = 0; t < 3; t++)
                    reinterpret_cast<float4*>(dst)[t] =
                        make_float4(v[4 * t], v[4 * t + 1], v[4 * t + 2], v[4 * t + 3]);
            } else {
                float v[40];
#pragma unroll
                for (int j = 0; j < 8; j++) {
                    const float a = row[8 * t3 + j];
#pragma unroll
                    for (int i = 0; i < 5; i++) v[5 * j + i] = a * tp[9 + i];
                }
                float* dst = feat_out + eg * 288 + 128 + 40 * t3;
#pragma unroll
                for (int t = 0; t < 10; t++)
                    reinterpret_cast<float4*>(dst)[t] =
                        make_float4(v[4 * t], v[4 * t + 1], v[4 * t + 2], v[4 * t + 3]);
            }
            __syncwarp();
        }
    }
}

extern "C" void kernel_launch(void* const* d_in, const int* in_sizes, int n_in,
                              void* d_out, int out_size)
{
    const int*   eidx   = (const int*)  d_in[0];
    const float* esh    = (const float*)d_in[1];
    const float* elen   = (const float*)d_in[2];
    const float* onehot = (const float*)d_in[3];
    const float* bw     = (const float*)d_in[4];
    const float* tpw    = (const float*)d_in[5];
    const float* W0     = (const float*)d_in[6];
    const float* W1     = (const float*)d_in[7];
    const float* We     = (const float*)d_in[8];
    float* out = (float*)d_out;

    const int E = in_sizes[0] / 2;       // 524288
    const int blocks = E / EPB;          // 2048

    combo_kernel<<<64, 160>>>(W1, We);
    afrag_kernel<<<(9216 + 255) / 256, 256>>>(W1);

    cudaFuncSetAttribute(e3_mma_kernel,
                         cudaFuncAttributeMaxDynamicSharedMemorySize, SMEM_BYTES);
    e3_mma_kernel<<<blocks, TPB, SMEM_BYTES>>>(
        eidx, esh, elen, onehot, bw, tpw, W0, out, E);
}

// round 12
// speedup vs baseline: 1.0718x; 1.0718x over previous
#include <cuda_runtime.h>
#include <cuda_bf16.h>
#include <cstdint>

typedef unsigned long long u64;

// ---------------- config ----------------
constexpr int TPB = 256;        // 8 warps
constexpr int EPB = 256;        // 1 edge per thread; warp owns 32 edges

// smem byte offsets (A-frags now read straight from L2 — not staged)
constexpr int OFF_HHI = 0;               // h hi: 256 edges x 35 u32 = 35840B
constexpr int OFF_HLO = 35840;           // h lo: 35840B
constexpr int OFF_TP  = 71680;           // tp: 256 x 16 f32 = 16384B
constexpr int OFF_BUF = 88064;           // 8 warps x 288 f32 = 9216B (stride 36 rows)
constexpr int OFF_BES = 97280;           // bessel W0 rows: 512 f32 = 2048B
constexpr int OFF_CST = 99328;           // 16 f32
constexpr int SMEM_BYTES = 99392;        // x2 CTAs = 198,784B <= 227KB carveout

constexpr int BSTR = 36;                 // D-buf row stride in floats (16B aligned)

// ---------------- device scratch ----------------
__device__ float    g_wcombo[64 * 160];
__device__ __align__(16) uint32_t g_afrag_hi[9216];  // 18 mt x 4 kt x 32 lanes x 4 regs
__device__ __align__(16) uint32_t g_afrag_lo[9216];

__device__ __forceinline__ float silu_f(float v) { return v / (1.0f + __expf(-v)); }

// ---------------- prep 1: W_combo = (W1*S1) @ (We*S2) ----------------
__global__ void combo_kernel(const float* __restrict__ W1, const float* __restrict__ We) {
    constexpr float S1 = 1.6789f * 0.125f;
    constexpr float S2 = 0.08838834764831845f;
    __shared__ float w1row[128];
    const int r = blockIdx.x;
    const int c = threadIdx.x;
    if (c < 128) w1row[c] = W1[r * 128 + c];
    __syncthreads();
    float acc = 0.0f;
#pragma unroll 8
    for (int k = 0; k < 128; k++)
        acc = fmaf(w1row[k], __ldg(We + k * 160 + c), acc);
    g_wcombo[r * 160 + c] = acc * (S1 * S2);
}

// packed weight element A[m][k] (A = Bpack^T), m in [0,288)
__device__ __forceinline__ float apack_val(int k, int m, const float* __restrict__ W1) {
    constexpr float S1 = 1.6789f * 0.125f;
    if (m < 128) return W1[k * 128 + m] * S1;
    if (m < 192) { int p = (m - 128) >> 1, s = (m - 128) & 1; return g_wcombo[k * 160 + p + 32 * s]; }
    if (m < 256) { int p = (m - 192) >> 1, s = (m - 192) & 1; return g_wcombo[k * 160 + 64 + p + 32 * s]; }
    return g_wcombo[k * 160 + 128 + (m - 256)];
}

// ---------------- prep 2: A fragments (hi/lo bf16) in mma order ----------------
__global__ void afrag_kernel(const float* __restrict__ W1) {
    int idx = blockIdx.x * blockDim.x + threadIdx.x;
    if (idx >= 9216) return;
    int ri = idx & 3, t = (idx >> 2) & 31, kt = (idx >> 7) & 3, mt = idx >> 9;
    int m  = mt * 16 + (t >> 2) + (ri & 1) * 8;
    int k0 = kt * 16 + (t & 3) * 2 + (ri >> 1) * 8;
    uint32_t hi = 0, lo = 0;
#pragma unroll
    for (int hv = 0; hv < 2; hv++) {
        float val = apack_val(k0 + hv, m, W1);
        __nv_bfloat16 h = __float2bfloat16(val);
        float rem = val - __bfloat162float(h);
        __nv_bfloat16 l = __float2bfloat16(rem);
        hi |= (uint32_t)__bfloat16_as_ushort(h) << (16 * hv);
        lo |= (uint32_t)__bfloat16_as_ushort(l) << (16 * hv);
    }
    g_afrag_hi[idx] = hi;
    g_afrag_lo[idx] = lo;
}

// ---------------- mma helper ----------------
__device__ __forceinline__ void mma16816(float* d, const uint4& a, uint32_t b0, uint32_t b1) {
    asm volatile(
        "mma.sync.aligned.m16n8k16.row.col.f32.bf16.bf16.f32 "
        "{%0,%1,%2,%3}, {%4,%5,%6,%7}, {%8,%9}, {%0,%1,%2,%3};"
        : "+f"(d[0]), "+f"(d[1]), "+f"(d[2]), "+f"(d[3])
        : "r"(a.x), "r"(a.y), "r"(a.z), "r"(a.w), "r"(b0), "r"(b1));
}

// ---------------- main kernel ----------------
__global__ void __launch_bounds__(TPB, 2)
e3_mma_kernel(const int*   __restrict__ eidx,
              const float* __restrict__ esh,
              const float* __restrict__ elen,
              const float* __restrict__ onehot,
              const float* __restrict__ bw,
              const float* __restrict__ tpw,
              const float* __restrict__ W0,
              float*       __restrict__ out,
              int E)
{
    extern __shared__ __align__(16) char smc[];
    const int tid  = threadIdx.x;
    const int warp = tid >> 5;
    const int lane = tid & 31;
    const int t3   = lane & 3;
    const int g    = lane >> 2;

    // ---- small cooperative loads ----
    {
        float* bes = reinterpret_cast<float*>(smc + OFF_BES);
        bes[tid]       = W0[32 * 64 + tid];
        bes[tid + 256] = W0[32 * 64 + 256 + tid];
        float* cst = reinterpret_cast<float*>(smc + OFF_CST);
        if (tid < 8)       cst[tid] = bw[tid];
        else if (tid < 15) cst[tid] = tpw[tid - 8];
    }
    __syncthreads();

    const float* bes = reinterpret_cast<const float*>(smc + OFF_BES);
    const float* cst = reinterpret_cast<const float*>(smc + OFF_CST);
    float* tparr = reinterpret_cast<float*>(smc + OFF_TP);

    float* __restrict__ lat_out  = out;
    float* __restrict__ feat_out = out + (size_t)E * 128;
    float* __restrict__ cut_out  = out + (size_t)E * 416;

    // ================= stage 1: per-thread edge =================
    {
        const int e = blockIdx.x * EPB + tid;
        const int   src = eidx[e];
        const int   dst = eidx[E + e];
        const float r   = elen[e];
        const float4 shv = reinterpret_cast<const float4*>(esh)[e];

        int ts = 0, td = 0;
        {
            const float4* rs = reinterpret_cast<const float4*>(onehot + (size_t)src * 16);
            const float4* rd = reinterpret_cast<const float4*>(onehot + (size_t)dst * 16);
#pragma unroll
            for (int q4 = 0; q4 < 4; q4++) {
                float4 a = __ldg(rs + q4); float4 b = __ldg(rd + q4);
                int base = q4 * 4;
                if (a.x > 0.5f) ts = base;     if (a.y > 0.5f) ts = base + 1;
                if (a.z > 0.5f) ts = base + 2; if (a.w > 0.5f) ts = base + 3;
                if (b.x > 0.5f) td = base;     if (b.y > 0.5f) td = base + 1;
                if (b.z > 0.5f) td = base + 2; if (b.w > 0.5f) td = base + 3;
            }
        }

        const float x    = r * 0.2f;
        const float invr = 1.0f / r;
        float eb[8];
#pragma unroll
        for (int j = 0; j < 8; j++)
            eb[j] = 0.4f * __sinf(cst[j] * x) * invr;

        const float x3 = x * x * x, x6 = x3 * x3, x7 = x6 * x, x8 = x7 * x;
        const float poly = 1.0f - 28.0f * x6 + 48.0f * x7 - 21.0f * x8;
        const float cutv = (x < 1.0f) ? poly : 0.0f;
        const float cl   = (cutv > 0.0f) ? cutv : 0.0f;
        cut_out[e] = cutv;

        // h = silu(S0*(W0[ts] + W0[16+td] + eb @ bessel_rows))
        constexpr float S0 = 0.15811388300841897f;
        float h[64];
        {
            const float4* rowts = reinterpret_cast<const float4*>(W0 + ts * 64);
            const float4* rowtd = reinterpret_cast<const float4*>(W0 + (16 + td) * 64);
#pragma unroll
            for (int q = 0; q < 16; q++) {
                float4 a = __ldg(rowts + q);
                float4 b = __ldg(rowtd + q);
                h[4 * q + 0] = a.x + b.x; h[4 * q + 1] = a.y + b.y;
                h[4 * q + 2] = a.z + b.z; h[4 * q + 3] = a.w + b.w;
            }
#pragma unroll
            for (int j = 0; j < 8; j++) {
                const float bj = eb[j];
                const float4* br = reinterpret_cast<const float4*>(bes + j * 64);
#pragma unroll
                for (int q = 0; q < 16; q++) {
                    float4 w = br[q];
                    h[4 * q + 0] = fmaf(bj, w.x, h[4 * q + 0]);
                    h[4 * q + 1] = fmaf(bj, w.y, h[4 * q + 1]);
                    h[4 * q + 2] = fmaf(bj, w.z, h[4 * q + 2]);
                    h[4 * q + 3] = fmaf(bj, w.w, h[4 * q + 3]);
                }
            }
        }

        // split h -> bf16 hi/lo; store pairs (stride 35 u32 per edge)
        uint32_t* hhw = reinterpret_cast<uint32_t*>(smc + OFF_HHI) + tid * 35;
        uint32_t* hlw = reinterpret_cast<uint32_t*>(smc + OFF_HLO) + tid * 35;
#pragma unroll
        for (int q = 0; q < 32; q++) {
            float v0 = silu_f(S0 * h[2 * q]);
            float v1 = silu_f(S0 * h[2 * q + 1]);
            __nv_bfloat16 h0 = __float2bfloat16(v0), h1 = __float2bfloat16(v1);
            float r0 = v0 - __bfloat162float(h0);
            float r1 = v1 - __bfloat162float(h1);
            __nv_bfloat16 l0 = __float2bfloat16(r0), l1 = __float2bfloat16(r1);
            hhw[q] = (uint32_t)__bfloat16_as_ushort(h0) | ((uint32_t)__bfloat16_as_ushort(h1) << 16);
            hlw[q] = (uint32_t)__bfloat16_as_ushort(l0) | ((uint32_t)__bfloat16_as_ushort(l1) << 16);
        }

        // tp scalars (cut + INV2 folded)
        constexpr float SQ3  = 1.7320508075688772f;
        constexpr float INV2 = 0.70710678118654752f;
        const float s = shv.x, vx = shv.y, vy = shv.z, vz = shv.w;
        const float tw0 = cst[8],  tw1 = cst[9],  tw2 = cst[10];
        const float tw3 = cst[11], tw4 = cst[12], tw5 = cst[13];
        const float tw6 = cst[14];
        const float sq   = s * s;
        const float dotv = (vx * vx + vy * vy + vz * vz) * (1.0f / SQ3);
        float* tp = tparr + tid * 16;
        tp[0] = cl;
        tp[1] = INV2 * (tw0 * sq + tw1 * dotv) * cl;
        tp[2] = INV2 * (tw4 * sq + tw5 * dotv) * cl;
        const float sa = INV2 * tw2 * s * cl;
        const float sb = INV2 * tw3 * s * cl;
        tp[3] = sa * vx; tp[4] = sa * vy; tp[5] = sa * vz;
        tp[6] = sb * vx; tp[7] = sb * vy; tp[8] = sb * vz;
        const float t6c = tw6 * cl;
        tp[9]  = t6c * SQ3 * vx * vy;
        tp[10] = t6c * SQ3 * vy * vz;
        tp[11] = t6c * (vz * vz - 0.5f * (vx * vx + vy * vy));
        tp[12] = t6c * SQ3 * vx * vz;
        tp[13] = t6c * (0.5f * SQ3) * (vx * vx - vy * vy);
    }
    __syncwarp();   // h/tp written & read within the same warp

    // ================= GEMM via mma.sync (A direct from L2) =================
    const uint4* afh = reinterpret_cast<const uint4*>(g_afrag_hi);
    const uint4* afl = reinterpret_cast<const uint4*>(g_afrag_lo);
    const uint32_t* hh = reinterpret_cast<const uint32_t*>(smc + OFF_HHI);
    const uint32_t* hl = reinterpret_cast<const uint32_t*>(smc + OFF_HLO);
    float* bwarp = reinterpret_cast<float*>(smc + OFF_BUF) + warp * (8 * BSTR);

#pragma unroll 1
    for (int c = 0; c < 9; c++) {
#pragma unroll 1
        for (int ngp = 0; ngp < 2; ngp++) {
            float acc[2][2][4];
#pragma unroll
            for (int a = 0; a < 2; a++)
#pragma unroll
                for (int b = 0; b < 2; b++)
#pragma unroll
                    for (int q = 0; q < 4; q++) acc[a][b][q] = 0.0f;

            const int eb0 = (warp * 32 + ngp * 16 + g) * 35 + t3;
            const int eb1 = eb0 + 8 * 35;

#pragma unroll
            for (int kt = 0; kt < 4; kt++) {
                const int ai = (2 * c * 4 + kt) * 32 + lane;
                const uint4 ah0 = __ldg(afh + ai);
                const uint4 ah1 = __ldg(afh + ai + 128);
                const uint4 al0 = __ldg(afl + ai);
                const uint4 al1 = __ldg(afl + ai + 128);
                const int ko = kt * 8;
                const uint32_t bh0a = hh[eb0 + ko], bh0b = hh[eb0 + ko + 4];
                const uint32_t bl0a = hl[eb0 + ko], bl0b = hl[eb0 + ko + 4];
                const uint32_t bh1a = hh[eb1 + ko], bh1b = hh[eb1 + ko + 4];
                const uint32_t bl1a = hl[eb1 + ko], bl1b = hl[eb1 + ko + 4];

                mma16816(acc[0][0], ah0, bh0a, bh0b);
                mma16816(acc[0][1], ah1, bh0a, bh0b);
                mma16816(acc[1][0], ah0, bh1a, bh1b);
                mma16816(acc[1][1], ah1, bh1a, bh1b);
                mma16816(acc[0][0], ah0, bl0a, bl0b);
                mma16816(acc[0][1], ah1, bl0a, bl0b);
                mma16816(acc[1][0], ah0, bl1a, bl1b);
                mma16816(acc[1][1], ah1, bl1a, bl1b);
                mma16816(acc[0][0], al0, bh0a, bh0b);
                mma16816(acc[0][1], al1, bh0a, bh0b);
                mma16816(acc[1][0], al0, bh1a, bh1b);
                mma16816(acc[1][1], al1, bh1a, bh1b);
            }

            // ---- epilogue per n-group ----
#pragma unroll 1
            for (int ng2 = 0; ng2 < 2; ng2++) {
                const int ng = 2 * ngp + ng2;
#pragma unroll
                for (int mtc = 0; mtc < 2; mtc++) {
                    bwarp[(2 * t3)     * BSTR + mtc * 16 + g]     = acc[ng2][mtc][0];
                    bwarp[(2 * t3 + 1) * BSTR + mtc * 16 + g]     = acc[ng2][mtc][1];
                    bwarp[(2 * t3)     * BSTR + mtc * 16 + g + 8] = acc[ng2][mtc][2];
                    bwarp[(2 * t3 + 1) * BSTR + mtc * 16 + g + 8] = acc[ng2][mtc][3];
                }
                __syncwarp();

                const int el = warp * 32 + ng * 8 + g;          // block-local edge
                const size_t eg = (size_t)blockIdx.x * EPB + el;
                const float* tp  = tparr + el * 16;
                const float* row = bwarp + g * BSTR;

                if (c < 4) {
                    const float cl = tp[0];
#pragma unroll
                    for (int h2 = 0; h2 < 2; h2++) {
                        float4 v = *reinterpret_cast<const float4*>(row + t3 * 8 + 4 * h2);
                        v.x *= cl; v.y *= cl; v.z *= cl; v.w *= cl;
                        *reinterpret_cast<float4*>(lat_out + eg * 128 + c * 32 + t3 * 8 + 4 * h2) = v;
                    }
                } else if (c < 6) {
                    const float ta = tp[1], tb = tp[2];
                    float4 v;
                    v.x = row[8 * t3 + 0] * ta + row[8 * t3 + 1] * tb;
                    v.y = row[8 * t3 + 2] * ta + row[8 * t3 + 3] * tb;
                    v.z = row[8 * t3 + 4] * ta + row[8 * t3 + 5] * tb;
                    v.w = row[8 * t3 + 6] * ta + row[8 * t3 + 7] * tb;
                    *reinterpret_cast<float4*>(feat_out + eg * 288 + (c - 4) * 16 + 4 * t3) = v;
                } else if (c < 8) {
                    float v[12];
#pragma unroll
                    for (int j = 0; j < 4; j++) {
                        const float a = row[8 * t3 + 2 * j], b = row[8 * t3 + 2 * j + 1];
                        v[3 * j + 0] = a * tp[3] + b * tp[6];
                        v[3 * j + 1] = a * tp[4] + b * tp[7];
                        v[3 * j + 2] = a * tp[5] + b * tp[8];
                    }
                    float* dst = feat_out + eg * 288 + 32 + (c - 6) * 48 + 12 * t3;
#pragma unroll
                    for (int t = 0; t < 3; t++)
                        reinterpret_cast<float4*>(dst)[t] =
                            make_float4(v[4 * t], v[4 * t + 1], v[4 * t + 2], v[4 * t + 3]);
                } else {
                    float v[40];
#pragma unroll
                    for (int j = 0; j < 8; j++) {
                        const float a = row[8 * t3 + j];
#pragma unroll
                        for (int i = 0; i < 5; i++) v[5 * j + i] = a * tp[9 + i];
                    }
                    float* dst = feat_out + eg * 288 + 128 + 40 * t3;
#pragma unroll
                    for (int t = 0; t < 10; t++)
                        reinterpret_cast<float4*>(dst)[t] =
                            make_float4(v[4 * t], v[4 * t + 1], v[4 * t + 2], v[4 * t + 3]);
                }
                __syncwarp();
            }
        }
    }
}

extern "C" void kernel_launch(void* const* d_in, const int* in_sizes, int n_in,
                              void* d_out, int out_size)
{
    const int*   eidx   = (const int*)  d_in[0];
    const float* esh    = (const float*)d_in[1];
    const float* elen   = (const float*)d_in[2];
    const float* onehot = (const float*)d_in[3];
    const float* bw     = (const float*)d_in[4];
    const float* tpw    = (const float*)d_in[5];
    const float* W0     = (const float*)d_in[6];
    const float* W1     = (const float*)d_in[7];
    const float* We     = (const float*)d_in[8];
    float* out = (float*)d_out;

    const int E = in_sizes[0] / 2;       // 524288
    const int blocks = E / EPB;          // 2048

    combo_kernel<<<64, 160>>>(W1, We);
    afrag_kernel<<<(9216 + 255) / 256, 256>>>(W1);

    cudaFuncSetAttribute(e3_mma_kernel,
                         cudaFuncAttributeMaxDynamicSharedMemorySize, SMEM_BYTES);
    e3_mma_kernel<<<blocks, TPB, SMEM_BYTES>>>(
        eidx, esh, elen, onehot, bw, tpw, W0, out, E);
}